// round 10
// baseline (speedup 1.0000x reference)
#include <cuda_runtime.h>
#include <stdint.h>

#define BETA      0.99f
#define T50       50
#define B_DIM     8192
#define IN_DIM    512
#define OUT_DIM   256

#define TILE_M    128
#define TILE_N    32
#define BK        16
#define ROW_ELEMS (OUT_DIM * T50)   // 12800

// smem union: GEMM tiles (As 16x132 + Bs 16x36 = 2688 words) and the
// per-pass packed mask (128 rows * 8 slots * 4 words = 4096 words).
// GEMM is fully done (trailing barrier) before the first mask write.
#define AS_OFF    0                 // float As[BK][132]
#define BS_OFF    (BK * 132)        // float Bs[BK][36]

__global__ __launch_bounds__(128, 4) void snn_fused5(
    const float* __restrict__ x,     // [B_DIM, IN_DIM]
    const float* __restrict__ W,     // [OUT_DIM, IN_DIM]
    const float* __restrict__ bias,  // [OUT_DIM]
    float* __restrict__ out)         // [B_DIM, OUT_DIM, T50]
{
    __shared__ __align__(16) uint32_t s_pool[4096];   // 16 KB union
    __shared__ float4 lut4[16];

    float* As = reinterpret_cast<float*>(s_pool) + AS_OFF;
    float* Bs = reinterpret_cast<float*>(s_pool) + BS_OFF;

    const int tid  = threadIdx.x;
    const int tx   = tid & 7;            // 8 col groups x 4 cols
    const int ty   = tid >> 3;           // 16 row groups x 8 rows
    const int col0 = blockIdx.x * TILE_N;
    const int row0 = blockIdx.y * TILE_M;

    if (tid < 16)                        // synced by first GEMM barrier
        lut4[tid] = make_float4((float)(tid & 1), (float)((tid >> 1) & 1),
                                (float)((tid >> 2) & 1), (float)((tid >> 3) & 1));

    // ---------------- GEMM: cur = x @ W^T + b  (k strictly ascending) -------
    float acc[32];                        // [row i 0..7][col j 0..3]
#pragma unroll
    for (int e = 0; e < 32; e++) acc[e] = 0.0f;

    const int lrow = tid >> 2;            // 0..31
    const int lc4  = (tid & 3) << 2;      // 0,4,8,12
    const float* xp = x + (size_t)(row0 + lrow) * IN_DIM + lc4;
    const float* wp = W + (size_t)(col0 + lrow) * IN_DIM + lc4;

    float4 va[4], vb;
#pragma unroll
    for (int q = 0; q < 4; q++)
        va[q] = *reinterpret_cast<const float4*>(xp + (size_t)(q * 32) * IN_DIM);
    vb = *reinterpret_cast<const float4*>(wp);

    for (int k0 = 0; k0 < IN_DIM; k0 += BK) {
#pragma unroll
        for (int q = 0; q < 4; q++) {
            int r = lrow + q * 32;
            As[(lc4 + 0) * 132 + r] = va[q].x;
            As[(lc4 + 1) * 132 + r] = va[q].y;
            As[(lc4 + 2) * 132 + r] = va[q].z;
            As[(lc4 + 3) * 132 + r] = va[q].w;
        }
        Bs[(lc4 + 0) * 36 + lrow] = vb.x;
        Bs[(lc4 + 1) * 36 + lrow] = vb.y;
        Bs[(lc4 + 2) * 36 + lrow] = vb.z;
        Bs[(lc4 + 3) * 36 + lrow] = vb.w;
        __syncthreads();

        if (k0 + BK < IN_DIM) {           // prefetch next chunk under FFMAs
#pragma unroll
            for (int q = 0; q < 4; q++)
                va[q] = *reinterpret_cast<const float4*>(
                    xp + (size_t)(q * 32) * IN_DIM + k0 + BK);
            vb = *reinterpret_cast<const float4*>(wp + k0 + BK);
        }

#pragma unroll
        for (int kk = 0; kk < BK; kk++) {
            float4 a0 = *reinterpret_cast<const float4*>(&As[kk * 132 + (ty << 3)]);
            float4 a1 = *reinterpret_cast<const float4*>(&As[kk * 132 + (ty << 3) + 4]);
            float4 b  = *reinterpret_cast<const float4*>(&Bs[kk * 36 + (tx << 2)]);
            float av[8] = {a0.x, a0.y, a0.z, a0.w, a1.x, a1.y, a1.z, a1.w};
            float bv[4] = {b.x, b.y, b.z, b.w};
#pragma unroll
            for (int i = 0; i < 8; i++)
#pragma unroll
                for (int j = 0; j < 4; j++)
                    acc[i * 4 + j] = fmaf(av[i], bv[j], acc[i * 4 + j]);
        }
        __syncthreads();
    }

    {   // bias add (plain fp32 add, same as all passing rounds)
        float4 b4 = *reinterpret_cast<const float4*>(&bias[col0 + (tx << 2)]);
        float bb[4] = {b4.x, b4.y, b4.z, b4.w};
#pragma unroll
        for (int i = 0; i < 8; i++)
#pragma unroll
            for (int j = 0; j < 4; j++)
                acc[i * 4 + j] = acc[i * 4 + j] + bb[j];
    }

    // ------------ Recurrence + writeout in 2 column-parity passes -----------
    // Pass p handles each thread's local cols {2p, 2p+1} (global col pair
    // tx*4 + 2p). Mask slot layout: s_pool[(rowInTile*8 + tx)*4 .. +4).
    const int lane = tid & 31;
    const int warp = tid >> 5;
    const int word = lane >> 3;           // expansion constants
    const int shft = (lane << 2) & 31;
    float4* out4 = reinterpret_cast<float4*>(out);
    const size_t colbase4 = (size_t)blockIdx.x * (TILE_N * T50 / 4);  // 400 float4

#pragma unroll
    for (int p = 0; p < 2; p++) {
        // -- recurrence for 8 rows x 2 cols, two rows at a time (4 chains) --
#pragma unroll
        for (int i2 = 0; i2 < 8; i2 += 2) {
            float c0 = acc[i2 * 4 + 2 * p],       c1 = acc[i2 * 4 + 2 * p + 1];
            float c2 = acc[(i2 + 1) * 4 + 2 * p], c3 = acc[(i2 + 1) * 4 + 2 * p + 1];
            float m0 = 0.f, m1 = 0.f, m2 = 0.f, m3 = 0.f;
            bool  s0 = false, s1 = false, s2 = false, s3 = false;
            uint32_t lo0 = 0, lo1 = 0, lo2 = 0, lo3 = 0;
            uint32_t hi0 = 0, hi1 = 0, hi2 = 0, hi3 = 0;

#pragma unroll
            for (int t = 0; t < T50; t++) {
                float t0 = __fadd_rn(__fmul_rn(BETA, m0), c0);
                float t1 = __fadd_rn(__fmul_rn(BETA, m1), c1);
                float t2 = __fadd_rn(__fmul_rn(BETA, m2), c2);
                float t3 = __fadd_rn(__fmul_rn(BETA, m3), c3);
                m0 = s0 ? __fadd_rn(t0, -1.0f) : t0;
                m1 = s1 ? __fadd_rn(t1, -1.0f) : t1;
                m2 = s2 ? __fadd_rn(t2, -1.0f) : t2;
                m3 = s3 ? __fadd_rn(t3, -1.0f) : t3;
                s0 = m0 > 1.0f; s1 = m1 > 1.0f; s2 = m2 > 1.0f; s3 = m3 > 1.0f;
                if (t < 32) {
                    lo0 |= s0 ? (1u << t) : 0u; lo1 |= s1 ? (1u << t) : 0u;
                    lo2 |= s2 ? (1u << t) : 0u; lo3 |= s3 ? (1u << t) : 0u;
                } else {
                    hi0 |= s0 ? (1u << (t - 32)) : 0u; hi1 |= s1 ? (1u << (t - 32)) : 0u;
                    hi2 |= s2 ? (1u << (t - 32)) : 0u; hi3 |= s3 ? (1u << (t - 32)) : 0u;
                }
            }

            // 100-bit stream pack per col pair (verified rounds 6/7):
            //  w0=c0[0:32) w1=c0[32:50)|c1[0:14)<<18 w2=c1[14:46) w3=c1[46:50)
            int r = (ty << 3) + i2;
            uint4 w;
            w.x = lo0;
            w.y = hi0 | (lo1 << 18);
            w.z = __funnelshift_r(lo1, hi1, 14);
            w.w = hi1 >> 14;
            *reinterpret_cast<uint4*>(&s_pool[((r << 3) + tx) << 2]) = w;
            w.x = lo2;
            w.y = hi2 | (lo3 << 18);
            w.z = __funnelshift_r(lo3, hi3, 14);
            w.w = hi3 >> 14;
            *reinterpret_cast<uint4*>(&s_pool[(((r + 1) << 3) + tx) << 2]) = w;
        }
        __syncthreads();

        // -- expansion: warp w owns rows [32w,32w+32); slot s -> global cols
        //    {4s+2p, 4s+2p+1}; 25 float4 per pair, lanes 0..24 --
        if (lane < 25) {
#pragma unroll 2
            for (int rr = 0; rr < 32; rr++) {
                int row = (warp << 5) + rr;
                const uint32_t* g = s_pool + (row << 5);      // 8 slots * 4 words
                float4* gr = out4 + (size_t)(row0 + row) * (ROW_ELEMS / 4)
                                  + colbase4 + 25 * p + lane;
#pragma unroll
                for (int s = 0; s < 8; s++) {
                    uint32_t nib = (g[(s << 2) + word] >> shft) & 0xFu;
                    __stcs(gr + 50 * s, lut4[nib]);
                }
            }
        }
        __syncthreads();                  // mask buffer reused by next pass
    }
}

extern "C" void kernel_launch(void* const* d_in, const int* in_sizes, int n_in,
                              void* d_out, int out_size)
{
    const float* x    = (const float*)d_in[0];   // [8192, 512]
    const float* W    = (const float*)d_in[1];   // [256, 512]
    const float* bias = (const float*)d_in[2];   // [256]
    float*       out  = (float*)d_out;           // [8192, 256, 50]

    dim3 grid(OUT_DIM / TILE_N, B_DIM / TILE_M); // (8, 64) = 512 blocks, 1 wave
    snn_fused5<<<grid, 128>>>(x, W, bias, out);
}

// round 11
// speedup vs baseline: 1.8564x; 1.8564x over previous
#include <cuda_runtime.h>
#include <stdint.h>

#define BETA      0.99f
#define T50       50
#define B_DIM     8192
#define IN_DIM    512
#define OUT_DIM   256

#define TILE_M    64          // batch rows per block
#define TILE_N    32          // output cols per block
#define BK        16
#define ROW_ELEMS (OUT_DIM * T50)   // 12800 floats per batch row

typedef unsigned long long ull;

__device__ __forceinline__ void fma2(ull& d, ull a, ull b) {
    asm("fma.rn.f32x2 %0, %1, %2, %0;" : "+l"(d) : "l"(a), "l"(b));
}
__device__ __forceinline__ ull dup2(float f) {
    ull r;
    asm("mov.b64 %0, {%1, %1};" : "=l"(r) : "f"(f));
    return r;
}

__global__ __launch_bounds__(128, 6) void snn_fused6(
    const float* __restrict__ x,     // [B_DIM, IN_DIM]
    const float* __restrict__ W,     // [OUT_DIM, IN_DIM]
    const float* __restrict__ bias,  // [OUT_DIM]
    float* __restrict__ out)         // [B_DIM, OUT_DIM, T50]
{
    __shared__ float As[BK][68];                // k-major, padded (rows contiguous)
    __shared__ float Bs[BK][36];
    __shared__ uint32_t s_msk[TILE_M * TILE_N * 2];   // 16 KB: [r][c][{lo,hi}]

    const int tid  = threadIdx.x;
    const int tx   = tid & 7;           // col group (4 cols each -> 32)
    const int ty   = tid >> 3;          // row group (4 rows each -> 64)
    const int col0 = blockIdx.x * TILE_N;
    const int row0 = blockIdx.y * TILE_M;

    // ---------------- GEMM: cur = x @ W^T + b  (k strictly ascending) -------
    // M-paired f32x2 accumulators: acc64[p*4+j] = (row 2p, row 2p+1) x col j.
    // Each 64-bit half is an independent fma.rn chain -> bit-identical to R5.
    ull acc64[8];
#pragma unroll
    for (int e = 0; e < 8; e++) acc64[e] = 0ull;

    const int lr = tid >> 2;            // 0..31
    const int lc = (tid & 3) << 2;      // 0,4,8,12
    const float* xp0 = x + (size_t)(row0 + lr) * IN_DIM + lc;
    const float* xp1 = xp0 + (size_t)32 * IN_DIM;
    const float* wp0 = W + (size_t)(col0 + lr) * IN_DIM + lc;

    float4 va0 = *reinterpret_cast<const float4*>(xp0);
    float4 va1 = *reinterpret_cast<const float4*>(xp1);
    float4 vb0 = *reinterpret_cast<const float4*>(wp0);

    for (int k0 = 0; k0 < IN_DIM; k0 += BK) {
        As[lc + 0][lr]      = va0.x; As[lc + 1][lr]      = va0.y;
        As[lc + 2][lr]      = va0.z; As[lc + 3][lr]      = va0.w;
        As[lc + 0][lr + 32] = va1.x; As[lc + 1][lr + 32] = va1.y;
        As[lc + 2][lr + 32] = va1.z; As[lc + 3][lr + 32] = va1.w;
        Bs[lc + 0][lr]      = vb0.x; Bs[lc + 1][lr]      = vb0.y;
        Bs[lc + 2][lr]      = vb0.z; Bs[lc + 3][lr]      = vb0.w;
        __syncthreads();

        if (k0 + BK < IN_DIM) {         // prefetch next chunk under the FFMAs
            va0 = *reinterpret_cast<const float4*>(xp0 + k0 + BK);
            va1 = *reinterpret_cast<const float4*>(xp1 + k0 + BK);
            vb0 = *reinterpret_cast<const float4*>(wp0 + k0 + BK);
        }

#pragma unroll
        for (int kk = 0; kk < BK; kk++) {
            // same LDS stream as the 127us kernel: 2x LDS.128 per kk
            ulonglong2 av = *reinterpret_cast<const ulonglong2*>(&As[kk][ty << 2]);
            float4 b  = *reinterpret_cast<const float4*>(&Bs[kk][tx << 2]);
            ull b0 = dup2(b.x), b1 = dup2(b.y), b2 = dup2(b.z), b3 = dup2(b.w);
            fma2(acc64[0], av.x, b0);  fma2(acc64[1], av.x, b1);
            fma2(acc64[2], av.x, b2);  fma2(acc64[3], av.x, b3);
            fma2(acc64[4], av.y, b0);  fma2(acc64[5], av.y, b1);
            fma2(acc64[6], av.y, b2);  fma2(acc64[7], av.y, b3);
        }
        __syncthreads();
    }

    float4 b4 = *reinterpret_cast<const float4*>(&bias[col0 + (tx << 2)]);
    const float bb[4] = {b4.x, b4.y, b4.z, b4.w};

    // ---------------- LIF recurrence (bit-exact, 4 chunks of 4) -------------
#pragma unroll
    for (int i = 0; i < 4; i++) {
        // extract currents for row i: half (i&1) of rowpair (i>>1); bias add
        // is the same single fp32 add as the passing rounds.
        float c0, c1, c2, c3;
        {
            const int p = (i >> 1) << 2;
            const int h = i & 1;
            float2 v0 = *reinterpret_cast<float2*>(&acc64[p + 0]);
            float2 v1 = *reinterpret_cast<float2*>(&acc64[p + 1]);
            float2 v2 = *reinterpret_cast<float2*>(&acc64[p + 2]);
            float2 v3 = *reinterpret_cast<float2*>(&acc64[p + 3]);
            c0 = (h ? v0.y : v0.x) + bb[0];
            c1 = (h ? v1.y : v1.x) + bb[1];
            c2 = (h ? v2.y : v2.x) + bb[2];
            c3 = (h ? v3.y : v3.x) + bb[3];
        }

        float m0 = 0.f, m1 = 0.f, m2 = 0.f, m3 = 0.f;
        bool  s0 = false, s1 = false, s2 = false, s3 = false;
        uint32_t lo0 = 0, lo1 = 0, lo2 = 0, lo3 = 0;
        uint32_t hi0 = 0, hi1 = 0, hi2 = 0, hi3 = 0;

#pragma unroll
        for (int t = 0; t < T50; t++) {
            float t0 = __fadd_rn(__fmul_rn(BETA, m0), c0);
            float t1 = __fadd_rn(__fmul_rn(BETA, m1), c1);
            float t2 = __fadd_rn(__fmul_rn(BETA, m2), c2);
            float t3 = __fadd_rn(__fmul_rn(BETA, m3), c3);
            m0 = s0 ? __fadd_rn(t0, -1.0f) : t0;
            m1 = s1 ? __fadd_rn(t1, -1.0f) : t1;
            m2 = s2 ? __fadd_rn(t2, -1.0f) : t2;
            m3 = s3 ? __fadd_rn(t3, -1.0f) : t3;
            s0 = m0 > 1.0f; s1 = m1 > 1.0f; s2 = m2 > 1.0f; s3 = m3 > 1.0f;
            if (t < 32) {
                lo0 |= s0 ? (1u << t) : 0u; lo1 |= s1 ? (1u << t) : 0u;
                lo2 |= s2 ? (1u << t) : 0u; lo3 |= s3 ? (1u << t) : 0u;
            } else {
                hi0 |= s0 ? (1u << (t - 32)) : 0u; hi1 |= s1 ? (1u << (t - 32)) : 0u;
                hi2 |= s2 ? (1u << (t - 32)) : 0u; hi3 |= s3 ? (1u << (t - 32)) : 0u;
            }
        }

        // rows of this thread: global row group ty, local rows i -> r = ty*4+i,
        // cols tx*4 .. +3. Mask layout identical to the 127us kernel.
        int r    = (ty << 2) + i;
        int base = ((r << 5) + (tx << 2)) << 1;     // (r*32 + c)*2
        *reinterpret_cast<uint2*>(&s_msk[base + 0]) = make_uint2(lo0, hi0);
        *reinterpret_cast<uint2*>(&s_msk[base + 2]) = make_uint2(lo1, hi1);
        *reinterpret_cast<uint2*>(&s_msk[base + 4]) = make_uint2(lo2, hi2);
        *reinterpret_cast<uint2*>(&s_msk[base + 6]) = make_uint2(lo3, hi3);
    }
    __syncthreads();

    // ---------------- Expansion + coalesced streaming writeout --------------
    // Verbatim from the 127us kernel.
    const int lane = tid & 31;
    const int warp = tid >> 5;

    int woff[4], shf[4];
#pragma unroll
    for (int u = 0; u < 4; u++) {
        int idx = lane * 4 + u;
        int cf  = (idx >= 50) ? 1 : 0;
        int t   = idx - 50 * cf;
        woff[u] = (cf << 1) + (t >> 5);
        shf[u]  = t & 31;
    }

    if (lane < 25) {
#pragma unroll
        for (int rr = 0; rr < 16; rr++) {
            int row = (warp << 4) + rr;
            const uint32_t* mrow = s_msk + (row << 6);      // 32 cols * 2 words
            float4* gout = reinterpret_cast<float4*>(
                out + (size_t)(row0 + row) * ROW_ELEMS + (size_t)col0 * T50);
#pragma unroll 4
            for (int cc = 0; cc < 16; cc++) {
                const uint32_t* g = mrow + (cc << 2);       // 2 cols = 4 words
                float4 v;
                v.x = __uint_as_float(((g[woff[0]] >> shf[0]) & 1u) * 0x3f800000u);
                v.y = __uint_as_float(((g[woff[1]] >> shf[1]) & 1u) * 0x3f800000u);
                v.z = __uint_as_float(((g[woff[2]] >> shf[2]) & 1u) * 0x3f800000u);
                v.w = __uint_as_float(((g[woff[3]] >> shf[3]) & 1u) * 0x3f800000u);
                __stcs(&gout[cc * 25 + lane], v);
            }
        }
    }
}

extern "C" void kernel_launch(void* const* d_in, const int* in_sizes, int n_in,
                              void* d_out, int out_size)
{
    const float* x    = (const float*)d_in[0];   // [8192, 512]
    const float* W    = (const float*)d_in[1];   // [256, 512]
    const float* bias = (const float*)d_in[2];   // [256]
    float*       out  = (float*)d_out;           // [8192, 256, 50]

    dim3 grid(OUT_DIM / TILE_N, B_DIM / TILE_M); // (8, 128) = 1024 blocks
    snn_fused6<<<grid, 128>>>(x, W, bias, out);
}